// round 15
// baseline (speedup 1.0000x reference)
#include <cuda_runtime.h>
#include <cstdint>

// FRIENDATTN persistent kernel: R10 + L2 prefetch depth (no smem/warp cost).
// Per friend-row n (N=16384): scores = x[n]·self[n/64] (L=50,D=128),
// w = softmax(scores); out[n] = sum_l w[l]*mask[n,l]*x[n,l,:].
//
// R10 (best, 69.6us / 79% DRAM) is a latency equilibrium: nothing saturated,
// per-row TMA fetch ~DRAM-tier latency only partly hidden by the 8-CTA
// stagger. R7 showed smem-funded depth fails (cost warps); R14 showed warps
// beyond 32/SM fail. This adds depth in L2 instead: each CTA issues
// cp.async.bulk.prefetch.L2 for the tile TWO rows ahead (62MB in flight
// chip-wide < 126MB L2), so the TMA g->s fill runs at L2-tier latency.
// Output stores use __stcs (evict-first) to keep L2 for prefetched tiles.

#define D_DIM 128
#define L_DIM 50
#define L_HALF 25
#define TPB   128
#define NROWS (256 * 64)
#define GRID  1216           // 152 SMs * 8 CTAs/SM

#define TILE_FLOATS (L_DIM * D_DIM)       // 6400
#define HALF_FLOATS (L_HALF * D_DIM)      // 3200
#define HALF_BYTES  (HALF_FLOATS * 4)     // 12800
#define TILE_BYTES  (TILE_FLOATS * 4)     // 25600
#define SELF_BYTES  (D_DIM * 4)           // 512

// dynamic SMEM layout (float index):
//  sx     [6400]  @ 0        (half0 @0, half1 @3200)
//  sself  [128]   @ 6400
//  sscore [64]    @ 6528
//  sw     [64]    @ 6592
//  mbar   [2]u64  @ 6656
#define OFF_SELF   6400
#define OFF_SCORE  6528
#define OFF_W      6592
#define OFF_MBAR   6656
#define SM_FLOATS  6660      // 26640 bytes -> 8 CTAs/SM

__device__ __forceinline__ unsigned int smem_u32(const void* p)
{
    return (unsigned int)__cvta_generic_to_shared(p);
}
__device__ __forceinline__ void mbar_init(unsigned int mbar, unsigned int count)
{
    asm volatile("mbarrier.init.shared.b64 [%0], %1;" :: "r"(mbar), "r"(count) : "memory");
}
__device__ __forceinline__ void mbar_expect_tx(unsigned int mbar, unsigned int bytes)
{
    asm volatile("mbarrier.arrive.expect_tx.shared.b64 _, [%0], %1;"
                 :: "r"(mbar), "r"(bytes) : "memory");
}
__device__ __forceinline__ void mbar_wait(unsigned int mbar, unsigned int phase)
{
    asm volatile(
        "{\n\t"
        ".reg .pred P;\n\t"
        "W%=:\n\t"
        "mbarrier.try_wait.parity.acquire.cta.shared::cta.b64 P, [%0], %1, 0x989680;\n\t"
        "@!P bra W%=;\n\t"
        "}"
        :: "r"(mbar), "r"(phase) : "memory");
}
__device__ __forceinline__ void bulk_g2s(unsigned int dst, const void* src,
                                         unsigned int bytes, unsigned int mbar)
{
    asm volatile(
        "cp.async.bulk.shared::cta.global.mbarrier::complete_tx::bytes [%0], [%1], %2, [%3];"
        :: "r"(dst), "l"(src), "r"(bytes), "r"(mbar) : "memory");
}
__device__ __forceinline__ void l2_prefetch(const void* src, unsigned int bytes)
{
    asm volatile("cp.async.bulk.prefetch.L2.global [%0], %1;"
                 :: "l"(src), "r"(bytes) : "memory");
}

__global__ __launch_bounds__(TPB) void friendattn_kernel(
    const float* __restrict__ x,        // [N, L, D]
    const float* __restrict__ self_x,   // [B, D]
    const void*  __restrict__ mask,     // [N, L]; dtype detected inline
    float* __restrict__ out)            // [N, D]
{
    extern __shared__ float smem[];
    const int tid  = threadIdx.x;
    const int lane = tid & 31;
    const int warp = tid >> 5;

    const unsigned int mbar0 = smem_u32(smem + OFF_MBAR);
    const unsigned int mbar1 = mbar0 + 8;

    // ---- inline mask dtype detection (first 2048 int32 words = 8KB, L2-hot) ----
    int gt1 = 0, odd_nz = 0, even_nz = 0;
    {
        const int* mw = (const int*)mask;
        #pragma unroll
        for (int it2 = 0; it2 < 16; ++it2) {
            int i = it2 * TPB + tid;
            unsigned int v = (unsigned int)mw[i];
            if (v > 1u) gt1 = 1;
            if (v != 0u) { if (i & 1) odd_nz = 1; else even_nz = 1; }
        }
    }
    const int any_gt1  = __syncthreads_or(gt1);
    const int any_odd  = __syncthreads_or(odd_nz);
    const int any_even = __syncthreads_or(even_nz);
    const int mode = any_gt1 ? 0 : ((!any_odd && any_even) ? 2 : 1);

    if (tid == 0) {
        mbar_init(mbar0, 1);
        mbar_init(mbar1, 1);
        asm volatile("fence.proxy.async.shared::cta;" ::: "memory");
    }
    __syncthreads();

    // half0 = l 0..24 (+self on mbar0), half1 = l 25..49 (mbar1)
    auto prefetch_half0 = [&](int row) {
        mbar_expect_tx(mbar0, HALF_BYTES + SELF_BYTES);
        bulk_g2s(smem_u32(smem), x + (size_t)row * TILE_FLOATS, HALF_BYTES, mbar0);
        bulk_g2s(smem_u32(smem + OFF_SELF),
                 self_x + (size_t)(row >> 6) * D_DIM, SELF_BYTES, mbar0);
    };
    auto prefetch_half1 = [&](int row) {
        mbar_expect_tx(mbar1, HALF_BYTES);
        bulk_g2s(smem_u32(smem + HALF_FLOATS),
                 x + (size_t)row * TILE_FLOATS + HALF_FLOATS, HALF_BYTES, mbar1);
    };

    int row = blockIdx.x;
    if (tid == 0 && row < NROWS) {
        prefetch_half0(row);
        prefetch_half1(row);
        // L2-prefetch the next tile too (depth-2 without smem)
        const int p1 = row + GRID;
        if (p1 < NROWS) l2_prefetch(x + (size_t)p1 * TILE_FLOATS, TILE_BYTES);
    }

    unsigned int phase = 0u;
    float* sscore = smem + OFF_SCORE;
    float* sw     = smem + OFF_W;

    while (row < NROWS) {
        // ---- L2 prefetch of the tile 2 rows ahead (no smem, no mbar) ----
        if (tid == 0) {
            const int p2 = row + 2 * GRID;
            if (p2 < NROWS) l2_prefetch(x + (size_t)p2 * TILE_FLOATS, TILE_BYTES);
        }

        // ---- softmax warp issues mask loads early (overlap with wait) ----
        float fm0 = 0.0f, fm1 = 0.0f;
        if (warp == 0) {
            const long long mbase = (long long)row * L_DIM;
            if (mode == 0) {
                const unsigned char* m = (const unsigned char*)mask + mbase;
                fm0 = m[lane] ? 1.0f : 0.0f;
                if (lane + 32 < L_DIM) fm1 = m[lane + 32] ? 1.0f : 0.0f;
            } else if (mode == 1) {
                const int* m = (const int*)mask + mbase;
                fm0 = m[lane] ? 1.0f : 0.0f;
                if (lane + 32 < L_DIM) fm1 = m[lane + 32] ? 1.0f : 0.0f;
            } else {
                const int* m = (const int*)mask + 2 * mbase;
                fm0 = m[2 * lane] ? 1.0f : 0.0f;
                if (lane + 32 < L_DIM) fm1 = m[2 * (lane + 32)] ? 1.0f : 0.0f;
            }
        }

        const float* sx = smem;

        // ---- scores half0 as soon as it lands ----
        mbar_wait(mbar0, phase);
        const float4 s4 = ((const float4*)(smem + OFF_SELF))[lane];
        for (int l = warp; l < L_HALF; l += 4) {
            float4 v = ((const float4*)(sx + l * D_DIM))[lane];
            float p = v.x * s4.x + v.y * s4.y + v.z * s4.z + v.w * s4.w;
            #pragma unroll
            for (int o = 16; o > 0; o >>= 1) p += __shfl_xor_sync(0xffffffffu, p, o);
            if (lane == 0) sscore[l] = p;
        }

        // ---- scores half1 ----
        mbar_wait(mbar1, phase);
        for (int l = L_HALF + warp; l < L_DIM; l += 4) {
            float4 v = ((const float4*)(sx + l * D_DIM))[lane];
            float p = v.x * s4.x + v.y * s4.y + v.z * s4.z + v.w * s4.w;
            #pragma unroll
            for (int o = 16; o > 0; o >>= 1) p += __shfl_xor_sync(0xffffffffu, p, o);
            if (lane == 0) sscore[l] = p;
        }
        phase ^= 1u;
        __syncthreads();                         // sscore complete

        // ---- softmax over L=50, mask folded in (warp 0) ----
        if (warp == 0) {
            float v0 = sscore[lane];
            float v1 = (lane + 32 < L_DIM) ? sscore[lane + 32] : -3.0e38f;
            float mx = fmaxf(v0, v1);
            #pragma unroll
            for (int o = 16; o > 0; o >>= 1) mx = fmaxf(mx, __shfl_xor_sync(0xffffffffu, mx, o));
            float e0 = __expf(v0 - mx);
            float e1 = (lane + 32 < L_DIM) ? __expf(v1 - mx) : 0.0f;
            float sum = e0 + e1;
            #pragma unroll
            for (int o = 16; o > 0; o >>= 1) sum += __shfl_xor_sync(0xffffffffu, sum, o);
            float inv = 1.0f / sum;
            sw[lane] = e0 * inv * fm0;
            if (lane + 32 < L_DIM) sw[lane + 32] = e1 * inv * fm1;
        }
        __syncthreads();

        const int nr = row + GRID;

        // ---- pooling half0, then refill half0 with next row ----
        float acc = 0.0f;
        #pragma unroll
        for (int l = 0; l < L_HALF; ++l)
            acc = fmaf(sw[l], sx[l * D_DIM + tid], acc);
        __syncthreads();                         // half0 + sself consumed
        if (tid == 0 && nr < NROWS) prefetch_half0(nr);

        // ---- pooling half1, then refill half1 ----
        #pragma unroll
        for (int l = L_HALF; l < L_DIM; ++l)
            acc = fmaf(sw[l], sx[l * D_DIM + tid], acc);
        __stcs(&out[(size_t)row * D_DIM + tid], acc);   // evict-first: keep L2 for tiles
        __syncthreads();                         // half1 + sw consumed
        if (tid == 0 && nr < NROWS) prefetch_half1(nr);

        row = nr;
    }
}

extern "C" void kernel_launch(void* const* d_in, const int* in_sizes, int n_in,
                              void* d_out, int out_size)
{
    const float* x      = (const float*)d_in[0];
    const float* self_x = (const float*)d_in[1];
    const void*  mask   = d_in[n_in - 1];
    float* out = (float*)d_out;

    cudaFuncSetAttribute(friendattn_kernel,
                         cudaFuncAttributeMaxDynamicSharedMemorySize,
                         SM_FLOATS * sizeof(float));

    friendattn_kernel<<<GRID, TPB, SM_FLOATS * sizeof(float)>>>(x, self_x, mask, out);
}

// round 16
// speedup vs baseline: 1.4236x; 1.4236x over previous
#include <cuda_runtime.h>
#include <cstdint>

// FRIENDATTN persistent kernel — FINAL (locked R10 configuration).
// Per friend-row n (N=16384): scores = x[n]·self[n/64] (L=50,D=128),
// w = softmax(scores); out[n] = sum_l w[l]*mask[n,l]*x[n,l,:].
//
// Roofline analysis: total traffic ~430MB at the B300 LTS cap (~6300 B/cyc,
// path-independent) gives a ~68.5us floor; this kernel runs at ~69.6us
// (~98.5% of it). Design: TMA bulk copies (no per-op LSU cost), 8 CTAs/SM
// (32 warps/SM — the measured occupancy knee), split-half tile with two
// mbarriers so half h is refilled with the next row right after pooling
// over it. Mask dtype (u8/int32/int64) detected inline from the first 8KB.

#define D_DIM 128
#define L_DIM 50
#define L_HALF 25
#define TPB   128
#define NROWS (256 * 64)
#define GRID  1216           // 152 SMs * 8 CTAs/SM

#define TILE_FLOATS (L_DIM * D_DIM)       // 6400
#define HALF_FLOATS (L_HALF * D_DIM)      // 3200
#define HALF_BYTES  (HALF_FLOATS * 4)     // 12800
#define SELF_BYTES  (D_DIM * 4)           // 512

// dynamic SMEM layout (float index):
//  sx     [6400]  @ 0        (half0 @0, half1 @3200)
//  sself  [128]   @ 6400
//  sscore [64]    @ 6528
//  sw     [64]    @ 6592
//  mbar   [2]u64  @ 6656
#define OFF_SELF   6400
#define OFF_SCORE  6528
#define OFF_W      6592
#define OFF_MBAR   6656
#define SM_FLOATS  6660      // 26640 bytes -> 8 CTAs/SM

__device__ __forceinline__ unsigned int smem_u32(const void* p)
{
    return (unsigned int)__cvta_generic_to_shared(p);
}
__device__ __forceinline__ void mbar_init(unsigned int mbar, unsigned int count)
{
    asm volatile("mbarrier.init.shared.b64 [%0], %1;" :: "r"(mbar), "r"(count) : "memory");
}
__device__ __forceinline__ void mbar_expect_tx(unsigned int mbar, unsigned int bytes)
{
    asm volatile("mbarrier.arrive.expect_tx.shared.b64 _, [%0], %1;"
                 :: "r"(mbar), "r"(bytes) : "memory");
}
__device__ __forceinline__ void mbar_wait(unsigned int mbar, unsigned int phase)
{
    asm volatile(
        "{\n\t"
        ".reg .pred P;\n\t"
        "W%=:\n\t"
        "mbarrier.try_wait.parity.acquire.cta.shared::cta.b64 P, [%0], %1, 0x989680;\n\t"
        "@!P bra W%=;\n\t"
        "}"
        :: "r"(mbar), "r"(phase) : "memory");
}
__device__ __forceinline__ void bulk_g2s(unsigned int dst, const void* src,
                                         unsigned int bytes, unsigned int mbar)
{
    asm volatile(
        "cp.async.bulk.shared::cta.global.mbarrier::complete_tx::bytes [%0], [%1], %2, [%3];"
        :: "r"(dst), "l"(src), "r"(bytes), "r"(mbar) : "memory");
}

__global__ __launch_bounds__(TPB) void friendattn_kernel(
    const float* __restrict__ x,        // [N, L, D]
    const float* __restrict__ self_x,   // [B, D]
    const void*  __restrict__ mask,     // [N, L]; dtype detected inline
    float* __restrict__ out)            // [N, D]
{
    extern __shared__ float smem[];
    const int tid  = threadIdx.x;
    const int lane = tid & 31;
    const int warp = tid >> 5;

    const unsigned int mbar0 = smem_u32(smem + OFF_MBAR);
    const unsigned int mbar1 = mbar0 + 8;

    // ---- inline mask dtype detection (first 2048 int32 words = 8KB, L2-hot) ----
    int gt1 = 0, odd_nz = 0, even_nz = 0;
    {
        const int* mw = (const int*)mask;
        #pragma unroll
        for (int it2 = 0; it2 < 16; ++it2) {
            int i = it2 * TPB + tid;
            unsigned int v = (unsigned int)mw[i];
            if (v > 1u) gt1 = 1;
            if (v != 0u) { if (i & 1) odd_nz = 1; else even_nz = 1; }
        }
    }
    const int any_gt1  = __syncthreads_or(gt1);
    const int any_odd  = __syncthreads_or(odd_nz);
    const int any_even = __syncthreads_or(even_nz);
    const int mode = any_gt1 ? 0 : ((!any_odd && any_even) ? 2 : 1);

    if (tid == 0) {
        mbar_init(mbar0, 1);
        mbar_init(mbar1, 1);
        asm volatile("fence.proxy.async.shared::cta;" ::: "memory");
    }
    __syncthreads();

    // half0 = l 0..24 (+self on mbar0), half1 = l 25..49 (mbar1)
    auto prefetch_half0 = [&](int row) {
        mbar_expect_tx(mbar0, HALF_BYTES + SELF_BYTES);
        bulk_g2s(smem_u32(smem), x + (size_t)row * TILE_FLOATS, HALF_BYTES, mbar0);
        bulk_g2s(smem_u32(smem + OFF_SELF),
                 self_x + (size_t)(row >> 6) * D_DIM, SELF_BYTES, mbar0);
    };
    auto prefetch_half1 = [&](int row) {
        mbar_expect_tx(mbar1, HALF_BYTES);
        bulk_g2s(smem_u32(smem + HALF_FLOATS),
                 x + (size_t)row * TILE_FLOATS + HALF_FLOATS, HALF_BYTES, mbar1);
    };

    int row = blockIdx.x;
    if (tid == 0 && row < NROWS) { prefetch_half0(row); prefetch_half1(row); }

    unsigned int phase = 0u;
    float* sscore = smem + OFF_SCORE;
    float* sw     = smem + OFF_W;

    while (row < NROWS) {
        // ---- softmax warp issues mask loads early (overlap with wait) ----
        float fm0 = 0.0f, fm1 = 0.0f;
        if (warp == 0) {
            const long long mbase = (long long)row * L_DIM;
            if (mode == 0) {
                const unsigned char* m = (const unsigned char*)mask + mbase;
                fm0 = m[lane] ? 1.0f : 0.0f;
                if (lane + 32 < L_DIM) fm1 = m[lane + 32] ? 1.0f : 0.0f;
            } else if (mode == 1) {
                const int* m = (const int*)mask + mbase;
                fm0 = m[lane] ? 1.0f : 0.0f;
                if (lane + 32 < L_DIM) fm1 = m[lane + 32] ? 1.0f : 0.0f;
            } else {
                const int* m = (const int*)mask + 2 * mbase;
                fm0 = m[2 * lane] ? 1.0f : 0.0f;
                if (lane + 32 < L_DIM) fm1 = m[2 * (lane + 32)] ? 1.0f : 0.0f;
            }
        }

        const float* sx = smem;

        // ---- scores half0 as soon as it lands ----
        mbar_wait(mbar0, phase);
        const float4 s4 = ((const float4*)(smem + OFF_SELF))[lane];
        for (int l = warp; l < L_HALF; l += 4) {
            float4 v = ((const float4*)(sx + l * D_DIM))[lane];
            float p = v.x * s4.x + v.y * s4.y + v.z * s4.z + v.w * s4.w;
            #pragma unroll
            for (int o = 16; o > 0; o >>= 1) p += __shfl_xor_sync(0xffffffffu, p, o);
            if (lane == 0) sscore[l] = p;
        }

        // ---- scores half1 ----
        mbar_wait(mbar1, phase);
        for (int l = L_HALF + warp; l < L_DIM; l += 4) {
            float4 v = ((const float4*)(sx + l * D_DIM))[lane];
            float p = v.x * s4.x + v.y * s4.y + v.z * s4.z + v.w * s4.w;
            #pragma unroll
            for (int o = 16; o > 0; o >>= 1) p += __shfl_xor_sync(0xffffffffu, p, o);
            if (lane == 0) sscore[l] = p;
        }
        phase ^= 1u;
        __syncthreads();                         // sscore complete

        // ---- softmax over L=50, mask folded in (warp 0) ----
        if (warp == 0) {
            float v0 = sscore[lane];
            float v1 = (lane + 32 < L_DIM) ? sscore[lane + 32] : -3.0e38f;
            float mx = fmaxf(v0, v1);
            #pragma unroll
            for (int o = 16; o > 0; o >>= 1) mx = fmaxf(mx, __shfl_xor_sync(0xffffffffu, mx, o));
            float e0 = __expf(v0 - mx);
            float e1 = (lane + 32 < L_DIM) ? __expf(v1 - mx) : 0.0f;
            float sum = e0 + e1;
            #pragma unroll
            for (int o = 16; o > 0; o >>= 1) sum += __shfl_xor_sync(0xffffffffu, sum, o);
            float inv = 1.0f / sum;
            sw[lane] = e0 * inv * fm0;
            if (lane + 32 < L_DIM) sw[lane + 32] = e1 * inv * fm1;
        }
        __syncthreads();

        const int nr = row + GRID;

        // ---- pooling half0, then refill half0 with next row ----
        float acc = 0.0f;
        #pragma unroll
        for (int l = 0; l < L_HALF; ++l)
            acc = fmaf(sw[l], sx[l * D_DIM + tid], acc);
        __syncthreads();                         // half0 + sself consumed
        if (tid == 0 && nr < NROWS) prefetch_half0(nr);

        // ---- pooling half1, then refill half1 ----
        #pragma unroll
        for (int l = L_HALF; l < L_DIM; ++l)
            acc = fmaf(sw[l], sx[l * D_DIM + tid], acc);
        out[(size_t)row * D_DIM + tid] = acc;
        __syncthreads();                         // half1 + sw consumed
        if (tid == 0 && nr < NROWS) prefetch_half1(nr);

        row = nr;
    }
}

extern "C" void kernel_launch(void* const* d_in, const int* in_sizes, int n_in,
                              void* d_out, int out_size)
{
    const float* x      = (const float*)d_in[0];
    const float* self_x = (const float*)d_in[1];
    const void*  mask   = d_in[n_in - 1];
    float* out = (float*)d_out;

    cudaFuncSetAttribute(friendattn_kernel,
                         cudaFuncAttributeMaxDynamicSharedMemorySize,
                         SM_FLOATS * sizeof(float));

    friendattn_kernel<<<GRID, TPB, SM_FLOATS * sizeof(float)>>>(x, self_x, mask, out);
}

// round 17
// speedup vs baseline: 1.4380x; 1.0101x over previous
#include <cuda_runtime.h>
#include <cstdint>

// FRIENDATTN persistent kernel — FINAL (locked; verified twice at ~69-70us).
// Per friend-row n (N=16384): scores = x[n]·self[n/64] (L=50,D=128),
// w = softmax(scores); out[n] = sum_l w[l]*mask[n,l]*x[n,l,:].
//
// Roofline: compulsory traffic ~430MB; measured ceiling for this pattern is
// ~6.3TB/s (three distinct kernel structures all plateau there), giving a
// ~68.5us floor. This kernel runs at ~68.7-69.6us kernel time (~99% of it).
// Design: TMA bulk copies (no per-op LSU issue cost), 8 CTAs/SM = 32 warps/SM
// (the measured occupancy knee), split-half tile with two mbarriers so each
// half is refilled with the next row's data immediately after being pooled.
// Mask dtype (u8 bool / int32 / int64) detected inline from the first 8KB.

#define D_DIM 128
#define L_DIM 50
#define L_HALF 25
#define TPB   128
#define NROWS (256 * 64)
#define GRID  1216           // 152 SMs * 8 CTAs/SM

#define TILE_FLOATS (L_DIM * D_DIM)       // 6400
#define HALF_FLOATS (L_HALF * D_DIM)      // 3200
#define HALF_BYTES  (HALF_FLOATS * 4)     // 12800
#define SELF_BYTES  (D_DIM * 4)           // 512

// dynamic SMEM layout (float index):
//  sx     [6400]  @ 0        (half0 @0, half1 @3200)
//  sself  [128]   @ 6400
//  sscore [64]    @ 6528
//  sw     [64]    @ 6592
//  mbar   [2]u64  @ 6656
#define OFF_SELF   6400
#define OFF_SCORE  6528
#define OFF_W      6592
#define OFF_MBAR   6656
#define SM_FLOATS  6660      // 26640 bytes -> 8 CTAs/SM

__device__ __forceinline__ unsigned int smem_u32(const void* p)
{
    return (unsigned int)__cvta_generic_to_shared(p);
}
__device__ __forceinline__ void mbar_init(unsigned int mbar, unsigned int count)
{
    asm volatile("mbarrier.init.shared.b64 [%0], %1;" :: "r"(mbar), "r"(count) : "memory");
}
__device__ __forceinline__ void mbar_expect_tx(unsigned int mbar, unsigned int bytes)
{
    asm volatile("mbarrier.arrive.expect_tx.shared.b64 _, [%0], %1;"
                 :: "r"(mbar), "r"(bytes) : "memory");
}
__device__ __forceinline__ void mbar_wait(unsigned int mbar, unsigned int phase)
{
    asm volatile(
        "{\n\t"
        ".reg .pred P;\n\t"
        "W%=:\n\t"
        "mbarrier.try_wait.parity.acquire.cta.shared::cta.b64 P, [%0], %1, 0x989680;\n\t"
        "@!P bra W%=;\n\t"
        "}"
        :: "r"(mbar), "r"(phase) : "memory");
}
__device__ __forceinline__ void bulk_g2s(unsigned int dst, const void* src,
                                         unsigned int bytes, unsigned int mbar)
{
    asm volatile(
        "cp.async.bulk.shared::cta.global.mbarrier::complete_tx::bytes [%0], [%1], %2, [%3];"
        :: "r"(dst), "l"(src), "r"(bytes), "r"(mbar) : "memory");
}

__global__ __launch_bounds__(TPB) void friendattn_kernel(
    const float* __restrict__ x,        // [N, L, D]
    const float* __restrict__ self_x,   // [B, D]
    const void*  __restrict__ mask,     // [N, L]; dtype detected inline
    float* __restrict__ out)            // [N, D]
{
    extern __shared__ float smem[];
    const int tid  = threadIdx.x;
    const int lane = tid & 31;
    const int warp = tid >> 5;

    const unsigned int mbar0 = smem_u32(smem + OFF_MBAR);
    const unsigned int mbar1 = mbar0 + 8;

    // ---- inline mask dtype detection (first 2048 int32 words = 8KB, L2-hot) ----
    int gt1 = 0, odd_nz = 0, even_nz = 0;
    {
        const int* mw = (const int*)mask;
        #pragma unroll
        for (int it2 = 0; it2 < 16; ++it2) {
            int i = it2 * TPB + tid;
            unsigned int v = (unsigned int)mw[i];
            if (v > 1u) gt1 = 1;
            if (v != 0u) { if (i & 1) odd_nz = 1; else even_nz = 1; }
        }
    }
    const int any_gt1  = __syncthreads_or(gt1);
    const int any_odd  = __syncthreads_or(odd_nz);
    const int any_even = __syncthreads_or(even_nz);
    const int mode = any_gt1 ? 0 : ((!any_odd && any_even) ? 2 : 1);

    if (tid == 0) {
        mbar_init(mbar0, 1);
        mbar_init(mbar1, 1);
        asm volatile("fence.proxy.async.shared::cta;" ::: "memory");
    }
    __syncthreads();

    // half0 = l 0..24 (+self on mbar0), half1 = l 25..49 (mbar1)
    auto prefetch_half0 = [&](int row) {
        mbar_expect_tx(mbar0, HALF_BYTES + SELF_BYTES);
        bulk_g2s(smem_u32(smem), x + (size_t)row * TILE_FLOATS, HALF_BYTES, mbar0);
        bulk_g2s(smem_u32(smem + OFF_SELF),
                 self_x + (size_t)(row >> 6) * D_DIM, SELF_BYTES, mbar0);
    };
    auto prefetch_half1 = [&](int row) {
        mbar_expect_tx(mbar1, HALF_BYTES);
        bulk_g2s(smem_u32(smem + HALF_FLOATS),
                 x + (size_t)row * TILE_FLOATS + HALF_FLOATS, HALF_BYTES, mbar1);
    };

    int row = blockIdx.x;
    if (tid == 0 && row < NROWS) { prefetch_half0(row); prefetch_half1(row); }

    unsigned int phase = 0u;
    float* sscore = smem + OFF_SCORE;
    float* sw     = smem + OFF_W;

    while (row < NROWS) {
        // ---- softmax warp issues mask loads early (overlap with wait) ----
        float fm0 = 0.0f, fm1 = 0.0f;
        if (warp == 0) {
            const long long mbase = (long long)row * L_DIM;
            if (mode == 0) {
                const unsigned char* m = (const unsigned char*)mask + mbase;
                fm0 = m[lane] ? 1.0f : 0.0f;
                if (lane + 32 < L_DIM) fm1 = m[lane + 32] ? 1.0f : 0.0f;
            } else if (mode == 1) {
                const int* m = (const int*)mask + mbase;
                fm0 = m[lane] ? 1.0f : 0.0f;
                if (lane + 32 < L_DIM) fm1 = m[lane + 32] ? 1.0f : 0.0f;
            } else {
                const int* m = (const int*)mask + 2 * mbase;
                fm0 = m[2 * lane] ? 1.0f : 0.0f;
                if (lane + 32 < L_DIM) fm1 = m[2 * (lane + 32)] ? 1.0f : 0.0f;
            }
        }

        const float* sx = smem;

        // ---- scores half0 as soon as it lands ----
        mbar_wait(mbar0, phase);
        const float4 s4 = ((const float4*)(smem + OFF_SELF))[lane];
        for (int l = warp; l < L_HALF; l += 4) {
            float4 v = ((const float4*)(sx + l * D_DIM))[lane];
            float p = v.x * s4.x + v.y * s4.y + v.z * s4.z + v.w * s4.w;
            #pragma unroll
            for (int o = 16; o > 0; o >>= 1) p += __shfl_xor_sync(0xffffffffu, p, o);
            if (lane == 0) sscore[l] = p;
        }

        // ---- scores half1 ----
        mbar_wait(mbar1, phase);
        for (int l = L_HALF + warp; l < L_DIM; l += 4) {
            float4 v = ((const float4*)(sx + l * D_DIM))[lane];
            float p = v.x * s4.x + v.y * s4.y + v.z * s4.z + v.w * s4.w;
            #pragma unroll
            for (int o = 16; o > 0; o >>= 1) p += __shfl_xor_sync(0xffffffffu, p, o);
            if (lane == 0) sscore[l] = p;
        }
        phase ^= 1u;
        __syncthreads();                         // sscore complete

        // ---- softmax over L=50, mask folded in (warp 0) ----
        if (warp == 0) {
            float v0 = sscore[lane];
            float v1 = (lane + 32 < L_DIM) ? sscore[lane + 32] : -3.0e38f;
            float mx = fmaxf(v0, v1);
            #pragma unroll
            for (int o = 16; o > 0; o >>= 1) mx = fmaxf(mx, __shfl_xor_sync(0xffffffffu, mx, o));
            float e0 = __expf(v0 - mx);
            float e1 = (lane + 32 < L_DIM) ? __expf(v1 - mx) : 0.0f;
            float sum = e0 + e1;
            #pragma unroll
            for (int o = 16; o > 0; o >>= 1) sum += __shfl_xor_sync(0xffffffffu, sum, o);
            float inv = 1.0f / sum;
            sw[lane] = e0 * inv * fm0;
            if (lane + 32 < L_DIM) sw[lane + 32] = e1 * inv * fm1;
        }
        __syncthreads();

        const int nr = row + GRID;

        // ---- pooling half0, then refill half0 with next row ----
        float acc = 0.0f;
        #pragma unroll
        for (int l = 0; l < L_HALF; ++l)
            acc = fmaf(sw[l], sx[l * D_DIM + tid], acc);
        __syncthreads();                         // half0 + sself consumed
        if (tid == 0 && nr < NROWS) prefetch_half0(nr);

        // ---- pooling half1, then refill half1 ----
        #pragma unroll
        for (int l = L_HALF; l < L_DIM; ++l)
            acc = fmaf(sw[l], sx[l * D_DIM + tid], acc);
        out[(size_t)row * D_DIM + tid] = acc;
        __syncthreads();                         // half1 + sw consumed
        if (tid == 0 && nr < NROWS) prefetch_half1(nr);

        row = nr;
    }
}

extern "C" void kernel_launch(void* const* d_in, const int* in_sizes, int n_in,
                              void* d_out, int out_size)
{
    const float* x      = (const float*)d_in[0];
    const float* self_x = (const float*)d_in[1];
    const void*  mask   = d_in[n_in - 1];
    float* out = (float*)d_out;

    cudaFuncSetAttribute(friendattn_kernel,
                         cudaFuncAttributeMaxDynamicSharedMemorySize,
                         SM_FLOATS * sizeof(float));

    friendattn_kernel<<<GRID, TPB, SM_FLOATS * sizeof(float)>>>(x, self_x, mask, out);
}